// round 1
// baseline (speedup 1.0000x reference)
#include <cuda_runtime.h>
#include <math.h>

#define NN 50000
#define EE 1600000
#define GG 64
#define ETOT (EE + NN)   // 1650000, divisible by 16

// ---------------- device scratch (no allocs allowed) ----------------
__device__ __align__(16) float g_loop_s[NN];
__device__ __align__(16) float g_loop_c[NN];
__device__ __align__(16) float g_loop_attr[NN];
__device__ __align__(16) float g_xl[NN * 64];
__device__ __align__(16) float g_xr[NN * 64];
__device__ __align__(16) float g_h1[NN * 64];
__device__ __align__(16) float g_h2[NN * 64];
__device__ __align__(16) float g_accum[NN * 64];
__device__ __align__(16) float g_logit[ETOT];
__device__ unsigned       g_m[NN];
__device__ __align__(16) float g_denom[NN];
__device__ __align__(16) float g_gsum[GG * 64];
__device__ float          g_gcnt[GG];

// monotone float <-> uint encoding for atomicMax over signed floats
__device__ __forceinline__ unsigned fenc(float f) {
    unsigned b = __float_as_uint(f);
    return (b & 0x80000000u) ? ~b : (b | 0x80000000u);
}
__device__ __forceinline__ float fdec(unsigned u) {
    return __uint_as_float((u & 0x80000000u) ? (u & 0x7FFFFFFFu) : ~u);
}
#define ENC_NEG_INF 0x007FFFFFu   // fenc(-inf)

// ---------------- init kernels ----------------
__global__ void k_init0() {
    int i = blockIdx.x * blockDim.x + threadIdx.x;
    if (i < NN) { g_loop_s[i] = 0.f; g_loop_c[i] = 0.f; }
    if (i < GG * 64) g_gsum[i] = 0.f;
    if (i < GG) g_gcnt[i] = 0.f;
}

__global__ void k_initlayer() {
    int i = blockIdx.x * blockDim.x + threadIdx.x;
    if (i < NN * 64) g_accum[i] = 0.f;
    if (i < NN) { g_m[i] = ENC_NEG_INF; g_denom[i] = 0.f; }
}

// ---------------- self-loop attr (fill_value='mean') ----------------
__global__ void k_loopsum(const int* __restrict__ dst, const float* __restrict__ ea) {
    int e = blockIdx.x * blockDim.x + threadIdx.x;
    if (e >= EE) return;
    int d = dst[e];
    atomicAdd(&g_loop_s[d], ea[e]);
    atomicAdd(&g_loop_c[d], 1.f);
}

__global__ void k_loopattr() {
    int n = blockIdx.x * blockDim.x + threadIdx.x;
    if (n >= NN) return;
    g_loop_attr[n] = g_loop_s[n] / fmaxf(g_loop_c[n], 1.f);
}

// ---------------- dense transform: out[n, 0:64] = X[n,:] @ W + b ----------------
// 256 threads, 64 nodes/block. Thread = (node group of 4) x (channel group of 4).
template <int K>
__global__ void k_gemm(const float* __restrict__ Xext, int x_is_h1, int out_is_xr,
                       const float* __restrict__ W, const float* __restrict__ bias) {
    __shared__ float Wsh[K * 64];
    const float* __restrict__ X = x_is_h1 ? g_h1 : Xext;
    float* __restrict__ out = out_is_xr ? g_xr : g_xl;

    int t = threadIdx.x;
    for (int i = t * 4; i < K * 64; i += 256 * 4)
        *(float4*)&Wsh[i] = *(const float4*)&W[i];
    __syncthreads();

    int cg = t & 15;           // channel group (4 channels)
    int ng = t >> 4;           // node group (4 nodes)
    int base = blockIdx.x * 64 + ng * 4;

    float4 b4 = *(const float4*)&bias[cg * 4];
    float4 acc0 = b4, acc1 = b4, acc2 = b4, acc3 = b4;

    int n0 = min(base + 0, NN - 1);
    int n1 = min(base + 1, NN - 1);
    int n2 = min(base + 2, NN - 1);
    int n3 = min(base + 3, NN - 1);

    const float* x0 = X + (size_t)n0 * K;
    const float* x1 = X + (size_t)n1 * K;
    const float* x2 = X + (size_t)n2 * K;
    const float* x3 = X + (size_t)n3 * K;

#pragma unroll 4
    for (int k = 0; k < K; k += 4) {
        float4 w0 = *(float4*)&Wsh[(k + 0) * 64 + cg * 4];
        float4 w1 = *(float4*)&Wsh[(k + 1) * 64 + cg * 4];
        float4 w2 = *(float4*)&Wsh[(k + 2) * 64 + cg * 4];
        float4 w3 = *(float4*)&Wsh[(k + 3) * 64 + cg * 4];
        float4 xa = __ldg((const float4*)(x0 + k));
        float4 xb = __ldg((const float4*)(x1 + k));
        float4 xc = __ldg((const float4*)(x2 + k));
        float4 xd = __ldg((const float4*)(x3 + k));
#define ACC(A, xq)                                                     \
        A.x = fmaf(xq.x, w0.x, A.x); A.y = fmaf(xq.x, w0.y, A.y);      \
        A.z = fmaf(xq.x, w0.z, A.z); A.w = fmaf(xq.x, w0.w, A.w);      \
        A.x = fmaf(xq.y, w1.x, A.x); A.y = fmaf(xq.y, w1.y, A.y);      \
        A.z = fmaf(xq.y, w1.z, A.z); A.w = fmaf(xq.y, w1.w, A.w);      \
        A.x = fmaf(xq.z, w2.x, A.x); A.y = fmaf(xq.z, w2.y, A.y);      \
        A.z = fmaf(xq.z, w2.z, A.z); A.w = fmaf(xq.z, w2.w, A.w);      \
        A.x = fmaf(xq.w, w3.x, A.x); A.y = fmaf(xq.w, w3.y, A.y);      \
        A.z = fmaf(xq.w, w3.z, A.z); A.w = fmaf(xq.w, w3.w, A.w);
        ACC(acc0, xa) ACC(acc1, xb) ACC(acc2, xc) ACC(acc3, xd)
#undef ACC
    }
    if (base + 0 < NN) *(float4*)&out[(size_t)(base + 0) * 64 + cg * 4] = acc0;
    if (base + 1 < NN) *(float4*)&out[(size_t)(base + 1) * 64 + cg * 4] = acc1;
    if (base + 2 < NN) *(float4*)&out[(size_t)(base + 2) * 64 + cg * 4] = acc2;
    if (base + 3 < NN) *(float4*)&out[(size_t)(base + 3) * 64 + cg * 4] = acc3;
}

// ---------------- edge pass A: logits + segment max ----------------
// 16 threads / edge, 16 edges / block
__global__ void k_edgeA(const int* __restrict__ src, const int* __restrict__ dst,
                        const float* __restrict__ eattr,
                        const float* __restrict__ We, const float* __restrict__ att) {
    int t = threadIdx.x;
    int e = blockIdx.x * 16 + (t >> 4);
    int cg = t & 15;
    if (e >= ETOT) return;   // grid is exact (ETOT % 16 == 0)

    int s, d; float ea;
    if (e < EE) { s = src[e]; d = dst[e]; ea = eattr[e]; }
    else        { s = d = e - EE; ea = g_loop_attr[e - EE]; }

    float4 a  = *(const float4*)&g_xl[(size_t)s * 64 + cg * 4];
    float4 b  = *(const float4*)&g_xr[(size_t)d * 64 + cg * 4];
    float4 w  = __ldg((const float4*)&We[cg * 4]);
    float4 at = __ldg((const float4*)&att[cg * 4]);

    float vx = a.x + b.x + ea * w.x;  vx = vx > 0.f ? vx : 0.2f * vx;
    float vy = a.y + b.y + ea * w.y;  vy = vy > 0.f ? vy : 0.2f * vy;
    float vz = a.z + b.z + ea * w.z;  vz = vz > 0.f ? vz : 0.2f * vz;
    float vw = a.w + b.w + ea * w.w;  vw = vw > 0.f ? vw : 0.2f * vw;

    float p = vx * at.x + vy * at.y + vz * at.z + vw * at.w;
    p += __shfl_xor_sync(0xffffffffu, p, 8);
    p += __shfl_xor_sync(0xffffffffu, p, 4);
    p += __shfl_xor_sync(0xffffffffu, p, 2);
    p += __shfl_xor_sync(0xffffffffu, p, 1);

    if (cg == 0) {
        g_logit[e] = p;
        atomicMax(&g_m[d], fenc(p));
    }
}

// ---------------- edge pass B: p = exp(logit - m), scatter p*xl[src], p ----------------
__global__ void k_edgeB(const int* __restrict__ src, const int* __restrict__ dst) {
    int t = threadIdx.x;
    int e = blockIdx.x * 16 + (t >> 4);
    int cg = t & 15;
    if (e >= ETOT) return;

    int s, d;
    if (e < EE) { s = src[e]; d = dst[e]; }
    else        { s = d = e - EE; }

    float m = fdec(g_m[d]);
    float p = __expf(g_logit[e] - m);
    if (cg == 0) atomicAdd(&g_denom[d], p);

    float4 a = *(const float4*)&g_xl[(size_t)s * 64 + cg * 4];
    float* ptr = &g_accum[(size_t)d * 64 + cg * 4];
    asm volatile("red.global.add.v4.f32 [%0], {%1, %2, %3, %4};"
                 :: "l"(ptr), "f"(a.x * p), "f"(a.y * p), "f"(a.z * p), "f"(a.w * p)
                 : "memory");
}

// ---------------- node finish: h = ELU(accum/denom + bias) ----------------
__global__ void k_nodefin(const float* __restrict__ bias, int out_is_h2) {
    int i = blockIdx.x * blockDim.x + threadIdx.x;
    if (i >= NN * 16) return;
    int n = i >> 4, cg = i & 15;
    float* __restrict__ out = out_is_h2 ? g_h2 : g_h1;

    float4 a = *(float4*)&g_accum[(size_t)n * 64 + cg * 4];
    float inv = 1.f / (g_denom[n] + 1e-16f);
    float4 b = __ldg((const float4*)&bias[cg * 4]);
    float x0 = a.x * inv + b.x;  x0 = x0 > 0.f ? x0 : expm1f(x0);
    float x1 = a.y * inv + b.y;  x1 = x1 > 0.f ? x1 : expm1f(x1);
    float x2 = a.z * inv + b.z;  x2 = x2 > 0.f ? x2 : expm1f(x2);
    float x3 = a.w * inv + b.w;  x3 = x3 > 0.f ? x3 : expm1f(x3);
    *(float4*)&out[(size_t)n * 64 + cg * 4] = make_float4(x0, x1, x2, x3);
}

// ---------------- global mean pool ----------------
__global__ void k_pool(const int* __restrict__ batch) {
    int i = blockIdx.x * blockDim.x + threadIdx.x;
    if (i >= NN * 16) return;
    int n = i >> 4, cg = i & 15;
    int g = batch[n];
    float4 h = *(float4*)&g_h2[(size_t)n * 64 + cg * 4];
    float* ptr = &g_gsum[g * 64 + cg * 4];
    asm volatile("red.global.add.v4.f32 [%0], {%1, %2, %3, %4};"
                 :: "l"(ptr), "f"(h.x), "f"(h.y), "f"(h.z), "f"(h.w)
                 : "memory");
    if (cg == 0) atomicAdd(&g_gcnt[g], 1.f);
}

// ---------------- head: relu(fc1) -> BN(eval) -> fc3 ----------------
__global__ void k_head(const float* __restrict__ Wfc1, const float* __restrict__ bfc1,
                       const float* __restrict__ gamma, const float* __restrict__ beta,
                       const float* __restrict__ mean, const float* __restrict__ var,
                       const float* __restrict__ Wfc3, const float* __restrict__ bfc3,
                       float* __restrict__ out) {
    int g = threadIdx.x;
    if (g >= GG) return;
    float cnt = fmaxf(g_gcnt[g], 1.f);
    float pooled[64];
#pragma unroll
    for (int c = 0; c < 64; c++) pooled[c] = g_gsum[g * 64 + c] / cnt;
    float acc = bfc3[0];
    for (int j = 0; j < 32; j++) {
        float z = bfc1[j];
#pragma unroll
        for (int c = 0; c < 64; c++) z = fmaf(pooled[c], Wfc1[c * 32 + j], z);
        z = fmaxf(z, 0.f);
        z = (z - mean[j]) * rsqrtf(var[j] + 1e-5f) * gamma[j] + beta[j];
        acc = fmaf(z, Wfc3[j], acc);
    }
    out[g] = acc;
}

// ---------------- launch ----------------
extern "C" void kernel_launch(void* const* d_in, const int* in_sizes, int n_in,
                              void* d_out, int out_size) {
    const float* x      = (const float*)d_in[0];
    const int*   eidx   = (const int*)d_in[1];
    const float* eattr  = (const float*)d_in[2];
    const int*   batch  = (const int*)d_in[3];
    const float* Wl1 = (const float*)d_in[4];   const float* bl1 = (const float*)d_in[5];
    const float* Wr1 = (const float*)d_in[6];   const float* br1 = (const float*)d_in[7];
    const float* We1 = (const float*)d_in[8];   const float* att1 = (const float*)d_in[9];
    const float* bias1 = (const float*)d_in[10];
    const float* Wl2 = (const float*)d_in[11];  const float* bl2 = (const float*)d_in[12];
    const float* Wr2 = (const float*)d_in[13];  const float* br2 = (const float*)d_in[14];
    const float* We2 = (const float*)d_in[15];  const float* att2 = (const float*)d_in[16];
    const float* bias2 = (const float*)d_in[17];
    const float* Wfc1 = (const float*)d_in[18]; const float* bfc1 = (const float*)d_in[19];
    const float* gamma = (const float*)d_in[20]; const float* beta = (const float*)d_in[21];
    const float* mean = (const float*)d_in[22];  const float* var = (const float*)d_in[23];
    const float* Wfc3 = (const float*)d_in[24];  const float* bfc3 = (const float*)d_in[25];
    float* out = (float*)d_out;

    const int* e_src = eidx;        // edge_index[0]
    const int* e_dst = eidx + EE;   // edge_index[1]

    const int TB = 256;
    const int nBlocksN   = (NN + TB - 1) / TB;
    const int nBlocksE   = (EE + TB - 1) / TB;
    const int nBlocksN64 = (NN * 64 + TB - 1) / TB;
    const int nBlocksEdge = (ETOT + 15) / 16;          // 16 edges per block
    const int nBlocksN16 = (NN * 16 + TB - 1) / TB;
    const int nBlocksGemm = (NN + 63) / 64;

    // self-loop mean attr
    k_init0<<<nBlocksN, TB>>>();
    k_loopsum<<<nBlocksE, TB>>>(e_dst, eattr);
    k_loopattr<<<nBlocksN, TB>>>();

    // ---- layer 1 ----
    k_gemm<128><<<nBlocksGemm, TB>>>(x, 0, 0, Wl1, bl1);   // -> g_xl
    k_gemm<128><<<nBlocksGemm, TB>>>(x, 0, 1, Wr1, br1);   // -> g_xr
    k_initlayer<<<nBlocksN64, TB>>>();
    k_edgeA<<<nBlocksEdge, TB>>>(e_src, e_dst, eattr, We1, att1);
    k_edgeB<<<nBlocksEdge, TB>>>(e_src, e_dst);
    k_nodefin<<<nBlocksN16, TB>>>(bias1, 0);               // -> g_h1

    // ---- layer 2 ----
    k_gemm<64><<<nBlocksGemm, TB>>>(nullptr, 1, 0, Wl2, bl2);  // g_h1 -> g_xl
    k_gemm<64><<<nBlocksGemm, TB>>>(nullptr, 1, 1, Wr2, br2);  // g_h1 -> g_xr
    k_initlayer<<<nBlocksN64, TB>>>();
    k_edgeA<<<nBlocksEdge, TB>>>(e_src, e_dst, eattr, We2, att2);
    k_edgeB<<<nBlocksEdge, TB>>>(e_src, e_dst);
    k_nodefin<<<nBlocksN16, TB>>>(bias2, 1);               // -> g_h2

    // ---- pool + head ----
    k_pool<<<nBlocksN16, TB>>>(batch);
    k_head<<<1, 64>>>(Wfc1, bfc1, gamma, beta, mean, var, Wfc3, bfc3, out);
}

// round 2
// speedup vs baseline: 1.5372x; 1.5372x over previous
#include <cuda_runtime.h>
#include <math.h>

#define NN 50000
#define EE 1600000
#define GG 64
#define ETOT (EE + NN)   // 1650000, divisible by 16

// ---------------- device scratch ----------------
__device__ __align__(16) float g_loop_s[NN];
__device__ __align__(16) float g_loop_c[NN];
__device__ __align__(16) float g_loop_attr[NN];
__device__ __align__(16) float g_xl[NN * 64];
__device__ __align__(16) float g_xr[NN * 64];
__device__ __align__(16) float g_accum[NN * 64];
__device__ __align__(16) float g_denom[NN];
__device__ __align__(16) float g_gsum[GG * 64];
__device__ float          g_gcnt[GG];

// ---------------- init ----------------
__global__ void k_init0() {
    int i = blockIdx.x * blockDim.x + threadIdx.x;
    if (i < NN) { g_loop_s[i] = 0.f; g_loop_c[i] = 0.f; }
    if (i < GG * 64) g_gsum[i] = 0.f;
    if (i < GG) g_gcnt[i] = 0.f;
}

__global__ void k_initlayer() {   // zero accum (vec4) + denom
    int i = blockIdx.x * blockDim.x + threadIdx.x;
    if (i < NN * 16) *(float4*)&g_accum[(size_t)i * 4] = make_float4(0.f, 0.f, 0.f, 0.f);
    if (i < NN) g_denom[i] = 0.f;
}

// ---------------- self-loop attr (fill_value='mean') ----------------
__global__ void k_loopsum(const int* __restrict__ dst, const float* __restrict__ ea) {
    int e = blockIdx.x * blockDim.x + threadIdx.x;
    if (e >= EE) return;
    int d = dst[e];
    atomicAdd(&g_loop_s[d], ea[e]);
    atomicAdd(&g_loop_c[d], 1.f);
}

__global__ void k_loopattr() {
    int n = blockIdx.x * blockDim.x + threadIdx.x;
    if (n >= NN) return;
    g_loop_attr[n] = g_loop_s[n] / fmaxf(g_loop_c[n], 1.f);
}

// ---------------- fused dual GEMM: xl = f(X)@Wl+bl, xr = f(X)@Wr+br ----------------
// Block: 256 threads, 64 nodes. X tile staged in SMEM (one global read per element).
// FUSE_ELU: instead of reading Xg, reconstruct h = ELU(accum/denom + ebias) on the fly.
template <int K, int FUSE_ELU>
__global__ __launch_bounds__(256) void k_gemm2(
        const float* __restrict__ Xg,
        const float* __restrict__ Wl, const float* __restrict__ bl,
        const float* __restrict__ Wr, const float* __restrict__ br,
        const float* __restrict__ ebias) {
    __shared__ float Xs[64 * K];
    int t = threadIdx.x;
    int base = blockIdx.x * 64;

    const int K4 = K / 4;
    for (int i = t; i < 64 * K4; i += 256) {
        int row = i / K4, c4 = i - row * K4;
        int node = base + row;
        float4 v = make_float4(0.f, 0.f, 0.f, 0.f);
        if (node < NN) {
            if (FUSE_ELU) {
                float4 a = *(const float4*)&g_accum[(size_t)node * 64 + c4 * 4];
                float inv = 1.f / (g_denom[node] + 1e-16f);
                float4 b = __ldg((const float4*)&ebias[c4 * 4]);
                v.x = a.x * inv + b.x;  v.x = v.x > 0.f ? v.x : expm1f(v.x);
                v.y = a.y * inv + b.y;  v.y = v.y > 0.f ? v.y : expm1f(v.y);
                v.z = a.z * inv + b.z;  v.z = v.z > 0.f ? v.z : expm1f(v.z);
                v.w = a.w * inv + b.w;  v.w = v.w > 0.f ? v.w : expm1f(v.w);
            } else {
                v = __ldg((const float4*)&Xg[(size_t)node * K + c4 * 4]);
            }
        }
        *(float4*)&Xs[row * K + c4 * 4] = v;
    }
    __syncthreads();

    int cg = t & 15;            // 4 output channels
    int ng = t >> 4;            // 4 nodes
    int nb = base + ng * 4;

    float4 bl4 = __ldg((const float4*)&bl[cg * 4]);
    float4 br4 = __ldg((const float4*)&br[cg * 4]);
    float4 l0 = bl4, l1 = bl4, l2 = bl4, l3 = bl4;
    float4 r0 = br4, r1 = br4, r2 = br4, r3 = br4;

    const float* xs0 = &Xs[(ng * 4 + 0) * K];
    const float* xs1 = &Xs[(ng * 4 + 1) * K];
    const float* xs2 = &Xs[(ng * 4 + 2) * K];
    const float* xs3 = &Xs[(ng * 4 + 3) * K];

#pragma unroll 2
    for (int k = 0; k < K; k += 4) {
        float4 wl0 = __ldg((const float4*)&Wl[(k + 0) * 64 + cg * 4]);
        float4 wl1 = __ldg((const float4*)&Wl[(k + 1) * 64 + cg * 4]);
        float4 wl2 = __ldg((const float4*)&Wl[(k + 2) * 64 + cg * 4]);
        float4 wl3 = __ldg((const float4*)&Wl[(k + 3) * 64 + cg * 4]);
        float4 wr0 = __ldg((const float4*)&Wr[(k + 0) * 64 + cg * 4]);
        float4 wr1 = __ldg((const float4*)&Wr[(k + 1) * 64 + cg * 4]);
        float4 wr2 = __ldg((const float4*)&Wr[(k + 2) * 64 + cg * 4]);
        float4 wr3 = __ldg((const float4*)&Wr[(k + 3) * 64 + cg * 4]);
        float4 xa = *(const float4*)(xs0 + k);
        float4 xb = *(const float4*)(xs1 + k);
        float4 xc = *(const float4*)(xs2 + k);
        float4 xd = *(const float4*)(xs3 + k);
#define ACC8(L, R, xq)                                                  \
        L.x = fmaf(xq.x, wl0.x, L.x); L.y = fmaf(xq.x, wl0.y, L.y);     \
        L.z = fmaf(xq.x, wl0.z, L.z); L.w = fmaf(xq.x, wl0.w, L.w);     \
        L.x = fmaf(xq.y, wl1.x, L.x); L.y = fmaf(xq.y, wl1.y, L.y);     \
        L.z = fmaf(xq.y, wl1.z, L.z); L.w = fmaf(xq.y, wl1.w, L.w);     \
        L.x = fmaf(xq.z, wl2.x, L.x); L.y = fmaf(xq.z, wl2.y, L.y);     \
        L.z = fmaf(xq.z, wl2.z, L.z); L.w = fmaf(xq.z, wl2.w, L.w);     \
        L.x = fmaf(xq.w, wl3.x, L.x); L.y = fmaf(xq.w, wl3.y, L.y);     \
        L.z = fmaf(xq.w, wl3.z, L.z); L.w = fmaf(xq.w, wl3.w, L.w);     \
        R.x = fmaf(xq.x, wr0.x, R.x); R.y = fmaf(xq.x, wr0.y, R.y);     \
        R.z = fmaf(xq.x, wr0.z, R.z); R.w = fmaf(xq.x, wr0.w, R.w);     \
        R.x = fmaf(xq.y, wr1.x, R.x); R.y = fmaf(xq.y, wr1.y, R.y);     \
        R.z = fmaf(xq.y, wr1.z, R.z); R.w = fmaf(xq.y, wr1.w, R.w);     \
        R.x = fmaf(xq.z, wr2.x, R.x); R.y = fmaf(xq.z, wr2.y, R.y);     \
        R.z = fmaf(xq.z, wr2.z, R.z); R.w = fmaf(xq.z, wr2.w, R.w);     \
        R.x = fmaf(xq.w, wr3.x, R.x); R.y = fmaf(xq.w, wr3.y, R.y);     \
        R.z = fmaf(xq.w, wr3.z, R.z); R.w = fmaf(xq.w, wr3.w, R.w);
        ACC8(l0, r0, xa) ACC8(l1, r1, xb) ACC8(l2, r2, xc) ACC8(l3, r3, xd)
#undef ACC8
    }
    if (nb + 0 < NN) { *(float4*)&g_xl[(size_t)(nb + 0) * 64 + cg * 4] = l0;
                       *(float4*)&g_xr[(size_t)(nb + 0) * 64 + cg * 4] = r0; }
    if (nb + 1 < NN) { *(float4*)&g_xl[(size_t)(nb + 1) * 64 + cg * 4] = l1;
                       *(float4*)&g_xr[(size_t)(nb + 1) * 64 + cg * 4] = r1; }
    if (nb + 2 < NN) { *(float4*)&g_xl[(size_t)(nb + 2) * 64 + cg * 4] = l2;
                       *(float4*)&g_xr[(size_t)(nb + 2) * 64 + cg * 4] = r2; }
    if (nb + 3 < NN) { *(float4*)&g_xl[(size_t)(nb + 3) * 64 + cg * 4] = l3;
                       *(float4*)&g_xr[(size_t)(nb + 3) * 64 + cg * 4] = r3; }
}

// ---------------- single fused edge pass (no segment-max: softmax is shift-invariant) ----
// 16 threads/edge: gather xl[src], xr[dst]; leakyrelu; logit; p = exp(logit);
// scatter p*xl[src] to accum[dst] and p to denom[dst].
__global__ void k_edge(const int* __restrict__ src, const int* __restrict__ dst,
                       const float* __restrict__ eattr,
                       const float* __restrict__ We, const float* __restrict__ att) {
    int t = threadIdx.x;
    int e = blockIdx.x * 16 + (t >> 4);
    int cg = t & 15;
    if (e >= ETOT) return;   // exact grid (ETOT % 16 == 0)

    int s, d; float ea;
    if (e < EE) { s = src[e]; d = dst[e]; ea = eattr[e]; }
    else        { s = d = e - EE; ea = g_loop_attr[e - EE]; }

    float4 a  = *(const float4*)&g_xl[(size_t)s * 64 + cg * 4];
    float4 b  = *(const float4*)&g_xr[(size_t)d * 64 + cg * 4];
    float4 w  = __ldg((const float4*)&We[cg * 4]);
    float4 at = __ldg((const float4*)&att[cg * 4]);

    float vx = a.x + b.x + ea * w.x;  vx = vx > 0.f ? vx : 0.2f * vx;
    float vy = a.y + b.y + ea * w.y;  vy = vy > 0.f ? vy : 0.2f * vy;
    float vz = a.z + b.z + ea * w.z;  vz = vz > 0.f ? vz : 0.2f * vz;
    float vw = a.w + b.w + ea * w.w;  vw = vw > 0.f ? vw : 0.2f * vw;

    float lg = vx * at.x + vy * at.y + vz * at.z + vw * at.w;
    lg += __shfl_xor_sync(0xffffffffu, lg, 8);
    lg += __shfl_xor_sync(0xffffffffu, lg, 4);
    lg += __shfl_xor_sync(0xffffffffu, lg, 2);
    lg += __shfl_xor_sync(0xffffffffu, lg, 1);

    float p = __expf(lg);
    if (cg == 0) atomicAdd(&g_denom[d], p);

    float* ptr = &g_accum[(size_t)d * 64 + cg * 4];
    asm volatile("red.global.add.v4.f32 [%0], {%1, %2, %3, %4};"
                 :: "l"(ptr), "f"(a.x * p), "f"(a.y * p), "f"(a.z * p), "f"(a.w * p)
                 : "memory");
}

// ---------------- final node pass: h2 = ELU(accum/denom + bias), fused mean-pool ------
__global__ void k_nodefin_pool(const float* __restrict__ bias, const int* __restrict__ batch) {
    int i = blockIdx.x * blockDim.x + threadIdx.x;
    if (i >= NN * 16) return;
    int n = i >> 4, cg = i & 15;

    float4 a = *(float4*)&g_accum[(size_t)n * 64 + cg * 4];
    float inv = 1.f / (g_denom[n] + 1e-16f);
    float4 b = __ldg((const float4*)&bias[cg * 4]);
    float x0 = a.x * inv + b.x;  x0 = x0 > 0.f ? x0 : expm1f(x0);
    float x1 = a.y * inv + b.y;  x1 = x1 > 0.f ? x1 : expm1f(x1);
    float x2 = a.z * inv + b.z;  x2 = x2 > 0.f ? x2 : expm1f(x2);
    float x3 = a.w * inv + b.w;  x3 = x3 > 0.f ? x3 : expm1f(x3);

    int g = batch[n];
    float* ptr = &g_gsum[g * 64 + cg * 4];
    asm volatile("red.global.add.v4.f32 [%0], {%1, %2, %3, %4};"
                 :: "l"(ptr), "f"(x0), "f"(x1), "f"(x2), "f"(x3)
                 : "memory");
    if (cg == 0) atomicAdd(&g_gcnt[g], 1.f);
}

// ---------------- head: relu(fc1) -> BN(eval) -> fc3 ----------------
__global__ void k_head(const float* __restrict__ Wfc1, const float* __restrict__ bfc1,
                       const float* __restrict__ gamma, const float* __restrict__ beta,
                       const float* __restrict__ mean, const float* __restrict__ var,
                       const float* __restrict__ Wfc3, const float* __restrict__ bfc3,
                       float* __restrict__ out) {
    int g = threadIdx.x;
    if (g >= GG) return;
    float cnt = fmaxf(g_gcnt[g], 1.f);
    float pooled[64];
#pragma unroll
    for (int c = 0; c < 64; c++) pooled[c] = g_gsum[g * 64 + c] / cnt;
    float acc = bfc3[0];
    for (int j = 0; j < 32; j++) {
        float z = bfc1[j];
#pragma unroll
        for (int c = 0; c < 64; c++) z = fmaf(pooled[c], Wfc1[c * 32 + j], z);
        z = fmaxf(z, 0.f);
        z = (z - mean[j]) * rsqrtf(var[j] + 1e-5f) * gamma[j] + beta[j];
        acc = fmaf(z, Wfc3[j], acc);
    }
    out[g] = acc;
}

// ---------------- launch ----------------
extern "C" void kernel_launch(void* const* d_in, const int* in_sizes, int n_in,
                              void* d_out, int out_size) {
    const float* x      = (const float*)d_in[0];
    const int*   eidx   = (const int*)d_in[1];
    const float* eattr  = (const float*)d_in[2];
    const int*   batch  = (const int*)d_in[3];
    const float* Wl1 = (const float*)d_in[4];   const float* bl1 = (const float*)d_in[5];
    const float* Wr1 = (const float*)d_in[6];   const float* br1 = (const float*)d_in[7];
    const float* We1 = (const float*)d_in[8];   const float* att1 = (const float*)d_in[9];
    const float* bias1 = (const float*)d_in[10];
    const float* Wl2 = (const float*)d_in[11];  const float* bl2 = (const float*)d_in[12];
    const float* Wr2 = (const float*)d_in[13];  const float* br2 = (const float*)d_in[14];
    const float* We2 = (const float*)d_in[15];  const float* att2 = (const float*)d_in[16];
    const float* bias2 = (const float*)d_in[17];
    const float* Wfc1 = (const float*)d_in[18]; const float* bfc1 = (const float*)d_in[19];
    const float* gamma = (const float*)d_in[20]; const float* beta = (const float*)d_in[21];
    const float* mean = (const float*)d_in[22];  const float* var = (const float*)d_in[23];
    const float* Wfc3 = (const float*)d_in[24];  const float* bfc3 = (const float*)d_in[25];
    float* out = (float*)d_out;

    const int* e_src = eidx;        // edge_index[0]
    const int* e_dst = eidx + EE;   // edge_index[1]

    const int TB = 256;
    const int nBlocksN    = (NN + TB - 1) / TB;
    const int nBlocksE    = (EE + TB - 1) / TB;
    const int nBlocksEdge = ETOT / 16;                  // 16 edges per block
    const int nBlocksN16  = (NN * 16 + TB - 1) / TB;
    const int nBlocksGemm = (NN + 63) / 64;

    // self-loop mean attr
    k_init0<<<nBlocksN, TB>>>();
    k_loopsum<<<nBlocksE, TB>>>(e_dst, eattr);
    k_loopattr<<<nBlocksN, TB>>>();

    // ---- layer 1 ----
    k_gemm2<128, 0><<<nBlocksGemm, TB>>>(x, Wl1, bl1, Wr1, br1, nullptr);
    k_initlayer<<<nBlocksN16, TB>>>();
    k_edge<<<nBlocksEdge, TB>>>(e_src, e_dst, eattr, We1, att1);

    // ---- layer 2 (ELU of layer-1 result fused into GEMM load) ----
    k_gemm2<64, 1><<<nBlocksGemm, TB>>>(nullptr, Wl2, bl2, Wr2, br2, bias1);
    k_initlayer<<<nBlocksN16, TB>>>();
    k_edge<<<nBlocksEdge, TB>>>(e_src, e_dst, eattr, We2, att2);

    // ---- finish layer 2 + pool + head ----
    k_nodefin_pool<<<nBlocksN16, TB>>>(bias2, batch);
    k_head<<<1, 64>>>(Wfc1, bfc1, gamma, beta, mean, var, Wfc3, bfc3, out);
}